// round 16
// baseline (speedup 1.0000x reference)
#include <cuda_runtime.h>
#include <cuda_bf16.h>
#include <stdint.h>

#define B_    8
#define L_    4096
#define D_    1024
#define A_    256
#define LC_   4352      // A_ + L_
#define KEEP_ 256
#define GRID_ 144       // <= SM count; one block per SM guaranteed
#define TPB_  512
#define BPB_  18        // blocks per batch in P0 (144/8)
#define NSLICE 18
#define GSLICE 9        // gather slices per batch (72 gather blocks / 8 batches)
#define SROWS 242       // ceil(4352/18)
#define GROWS 29        // ceil(256/9)

#define CDROP_ (0.1f / 4096.0f)                    // 0.1 / n_dropped
#define ALPHA_ (1.0f / 256.0f - 0.1f / 4096.0f)    // kept coefficient in ctx

// -------- scratch (device globals; no allocation allowed) --------
// zero-initialized at module load; thereafter reset by k_addproj each call
__device__ unsigned g_barrier[8];
__device__ unsigned g_uflag;      // release: u vector ready
__device__ unsigned g_kflag;      // release: kept ctx ready
__device__ unsigned g_gflag;      // release: gather done (72 blocks)
__device__ float g_sal[B_ * LC_];
__device__ float g_part[B_ * NSLICE * D_];
__device__ float g_kpart[B_ * GSLICE * D_];
__device__ int   g_topidx[B_ * KEEP_];
__device__ float g_u[B_ * D_];       // 0.9*cold + CDROP*totsum
__device__ float g_kctx[B_ * D_];    // ALPHA*keptsum
__device__ float g_proj1[B_ * D_];   // u @ W^T
__device__ float g_proj[B_ * D_];    // full proj

__device__ __forceinline__ void gbar(int ph) {
    __syncthreads();
    __threadfence();
    if (threadIdx.x == 0) {
        atomicAdd(&g_barrier[ph], 1u);
        while (atomicAdd(&g_barrier[ph], 0u) < (unsigned)GRID_) __nanosleep(32);
        __threadfence();
    }
    __syncthreads();
}

__device__ __forceinline__ unsigned int order_key(float f) {
    unsigned int u = __float_as_uint(f);
    return u ^ ((u >> 31) ? 0xFFFFFFFFu : 0x80000000u);
}

// ================= K1: persistent — salience .. gemv =================
__global__ void __launch_bounds__(TPB_, 1)
k_fused(const float* __restrict__ x,
        const float* __restrict__ active,
        const float* __restrict__ cold,
        const float* __restrict__ wsal,
        const float* __restrict__ wread,
        float* __restrict__ new_active,
        float* __restrict__ cold_out) {
    __shared__ __align__(16) char smem_raw[33024];
    __shared__ unsigned s_prefix;
    __shared__ int s_krem;

    const int blk  = blockIdx.x;
    const int tid  = threadIdx.x;
    const int warp = tid >> 5;
    const int lane = tid & 31;

    //================ P0: salience + per-block partial column sums ================
    {
        float* s_col = (float*)smem_raw;
        const int b  = blk / BPB_;
        const int sl = blk % BPB_;
        for (int i = tid; i < D_; i += TPB_) s_col[i] = 0.f;

        float4 ws[8];
#pragma unroll
        for (int k = 0; k < 8; k++)
            ws[k] = *(const float4*)(wsal + k * 128 + lane * 4);
        float4 cs[8];
#pragma unroll
        for (int k = 0; k < 8; k++) cs[k] = make_float4(0.f, 0.f, 0.f, 0.f);
        __syncthreads();

        const int row0   = sl * SROWS;
        const int rowend = min(LC_, row0 + SROWS);
        for (int t = row0 + warp; t < rowend; t += 16) {
            const float* src = (t < A_)
                ? active + ((size_t)b * A_ + t) * D_
                : x      + ((size_t)b * L_ + (t - A_)) * D_;
            float dot = 0.f;
#pragma unroll
            for (int k = 0; k < 8; k++) {
                float4 v = *(const float4*)(src + k * 128 + lane * 4);
                dot += v.x * ws[k].x + v.y * ws[k].y + v.z * ws[k].z + v.w * ws[k].w;
                cs[k].x += v.x; cs[k].y += v.y; cs[k].z += v.z; cs[k].w += v.w;
            }
#pragma unroll
            for (int o = 16; o > 0; o >>= 1)
                dot += __shfl_down_sync(0xffffffffu, dot, o);
            if (lane == 0) g_sal[b * LC_ + t] = dot;
        }
#pragma unroll
        for (int k = 0; k < 8; k++) {
            int d0 = k * 128 + lane * 4;
            atomicAdd(&s_col[d0 + 0], cs[k].x);
            atomicAdd(&s_col[d0 + 1], cs[k].y);
            atomicAdd(&s_col[d0 + 2], cs[k].z);
            atomicAdd(&s_col[d0 + 3], cs[k].w);
        }
        __syncthreads();
        float* dst = g_part + ((size_t)b * NSLICE + sl) * D_;
        for (int i = tid; i < D_ / 4; i += TPB_)
            ((float4*)dst)[i] = ((const float4*)s_col)[i];
    }
    gbar(0);

    //================ P1: u-reduce (0..7) || topk (8..15) || gemv1 u@W^T (16..79) ================
    if (blk < 8) {
        const int b = blk;
        for (int d = tid; d < D_; d += TPB_) {
            float tot = 0.f;
            const float* p = g_part + (size_t)b * NSLICE * D_ + d;
#pragma unroll
            for (int s = 0; s < NSLICE; s++) tot += p[(size_t)s * D_];
            g_u[b * D_ + d] = 0.9f * cold[b * D_ + d] + CDROP_ * tot;
        }
        __threadfence();
        __syncthreads();
        if (tid == 0) atomicAdd(&g_uflag, 1u);   // release
    } else if (blk < 16) {
        const int b = blk - 8;
        unsigned* skeys = (unsigned*)smem_raw;              // 4352 u32
        unsigned* hist  = (unsigned*)(smem_raw + 17408);
        int* out_idx    = (int*)(smem_raw + 18432);
        unsigned* wsum  = (unsigned*)(smem_raw + 19456);

        for (int i = tid; i < LC_; i += TPB_)
            skeys[i] = order_key(g_sal[b * LC_ + i]);
        if (tid == 0) { s_prefix = 0u; s_krem = KEEP_; }
        __syncthreads();

        for (int pass = 0; pass < 4; pass++) {
            const int shift = 24 - 8 * pass;
            if (tid < 256) hist[tid] = 0u;
            __syncthreads();
            const unsigned pfx = s_prefix;
            const int krem = s_krem;
            for (int i = tid; i < LC_; i += TPB_) {
                unsigned k = skeys[i];
                if (pass == 0 || (k >> (shift + 8)) == pfx)
                    atomicAdd(&hist[(k >> shift) & 255u], 1u);
            }
            __syncthreads();
            if (warp == 0) {
                unsigned h[8], suf[8];
                unsigned acc = 0u;
#pragma unroll
                for (int j = 7; j >= 0; j--) { h[j] = hist[lane * 8 + j]; acc += h[j]; suf[j] = acc; }
                const unsigned tot = acc;
                unsigned inc = tot;
#pragma unroll
                for (int off = 1; off < 32; off <<= 1) {
                    unsigned v = __shfl_down_sync(0xffffffffu, inc, off);
                    if (lane + off < 32) inc += v;
                }
                const unsigned after = inc - tot;
#pragma unroll
                for (int j = 0; j < 8; j++) {
                    unsigned S  = after + suf[j];
                    unsigned Sn = after + (j < 7 ? suf[j + 1] : 0u);
                    if (S >= (unsigned)krem && Sn < (unsigned)krem) {
                        s_prefix = (pfx << 8) | (unsigned)(lane * 8 + j);
                        s_krem   = krem - (int)Sn;
                    }
                }
            }
            __syncthreads();
        }

        const unsigned thr = s_prefix;
        const unsigned rem = (unsigned)s_krem;

        const int base = tid * 9;
        unsigned keys_l[9];
        unsigned gt = 0u, eq = 0u;
#pragma unroll
        for (int j = 0; j < 9; j++) {
            const int i = base + j;
            unsigned k = (i < LC_) ? skeys[i] : 0u;
            keys_l[j] = k;
            if (i < LC_) { gt += (k > thr); eq += (k == thr); }
        }
        const unsigned pair = (gt << 16) | eq;
        unsigned inc = pair;
#pragma unroll
        for (int off = 1; off < 32; off <<= 1) {
            unsigned v = __shfl_up_sync(0xffffffffu, inc, off);
            if (lane >= off) inc += v;
        }
        const unsigned excl = inc - pair;
        if (lane == 31) wsum[warp] = inc;
        __syncthreads();
        if (warp == 0) {
            unsigned v = (lane < 16) ? wsum[lane] : 0u;
            unsigned winc = v;
#pragma unroll
            for (int off = 1; off < 16; off <<= 1) {
                unsigned t = __shfl_up_sync(0xffffffffu, winc, off);
                if (lane >= off) winc += t;
            }
            if (lane < 16) wsum[lane] = winc - v;
        }
        __syncthreads();
        const unsigned basepair = excl + wsum[warp];
        unsigned gpref = basepair >> 16;
        unsigned epref = basepair & 0xFFFFu;
#pragma unroll
        for (int j = 0; j < 9; j++) {
            const int i = base + j;
            if (i < LC_) {
                const unsigned k = keys_l[j];
                if (k > thr) {
                    out_idx[gpref + (epref < rem ? epref : rem)] = i;
                    gpref++;
                } else if (k == thr) {
                    if (epref < rem) out_idx[gpref + epref] = i;
                    epref++;
                }
            }
        }
        __syncthreads();
        if (tid < KEEP_) g_topidx[b * KEEP_ + tid] = out_idx[tid];
    } else if (blk < 80) {
        // gemv1: proj1[b,e] = sum_d u[b,d]*wread[e,d]; W DRAM read hidden behind topk
        float4* sctx = (float4*)smem_raw;
        const int e = (blk - 16) * 16 + warp;
        const float* wr = wread + (size_t)e * D_ + lane * 4;
        float4 w[8];
#pragma unroll
        for (int k = 0; k < 8; k++)
            w[k] = *(const float4*)(wr + k * 128);

        if (tid == 0) {
            while (atomicAdd(&g_uflag, 0u) < 8u) __nanosleep(32);
        }
        __syncthreads();
        __threadfence();
        for (int i = tid; i < B_ * 256; i += TPB_)
            sctx[i] = ((const float4*)g_u)[i];
        __syncthreads();

        float acc[B_];
#pragma unroll
        for (int bb = 0; bb < B_; bb++) acc[bb] = 0.f;
#pragma unroll
        for (int k = 0; k < 8; k++) {
#pragma unroll
            for (int bb = 0; bb < B_; bb++) {
                float4 c = sctx[bb * 256 + k * 32 + lane];
                acc[bb] += w[k].x * c.x + w[k].y * c.y + w[k].z * c.z + w[k].w * c.w;
            }
        }
#pragma unroll
        for (int bb = 0; bb < B_; bb++) {
#pragma unroll
            for (int o = 16; o > 0; o >>= 1)
                acc[bb] += __shfl_down_sync(0xffffffffu, acc[bb], o);
            if (lane == 0) g_proj1[bb * D_ + e] = acc[bb];
        }
    }
    gbar(1);

    //================ P2': gather (72..143) || kept-reduce (0..7) || gemv2 (8..71) ================
    if (blk >= 72) {
        // ---- gather role: 72 blocks; batch = g/9, slice = g%9, 29 rows/slice ----
        float* s_col = (float*)smem_raw;
        const int g  = blk - 72;
        const int b  = g / GSLICE;
        const int sl = g % GSLICE;
        const int row0   = sl * GROWS;
        const int rowend = min(KEEP_, row0 + GROWS);
        for (int i = tid; i < D_; i += TPB_) s_col[i] = 0.f;
        __syncthreads();

        for (int r = row0 + warp; r < rowend; r += 16) {
            const int idx = g_topidx[b * KEEP_ + r];
            const float* src = (idx < A_)
                ? active + ((size_t)b * A_ + idx) * D_
                : x      + ((size_t)b * L_ + (idx - A_)) * D_;
            float* dst = new_active + ((size_t)b * KEEP_ + r) * D_;
            float4 v[8];
#pragma unroll
            for (int k = 0; k < 8; k++)
                v[k] = *(const float4*)(src + k * 128 + lane * 4);
#pragma unroll
            for (int k = 0; k < 8; k++) {
                *(float4*)(dst + k * 128 + lane * 4) = v[k];
                int d0 = k * 128 + lane * 4;
                atomicAdd(&s_col[d0 + 0], v[k].x);
                atomicAdd(&s_col[d0 + 1], v[k].y);
                atomicAdd(&s_col[d0 + 2], v[k].z);
                atomicAdd(&s_col[d0 + 3], v[k].w);
            }
        }
        __syncthreads();
        float* kp = g_kpart + ((size_t)b * GSLICE + sl) * D_;
        for (int i = tid; i < D_ / 4; i += TPB_)
            ((float4*)kp)[i] = ((const float4*)s_col)[i];
        __threadfence();
        __syncthreads();
        if (tid == 0) atomicAdd(&g_gflag, 1u);   // release gather
    } else if (blk < 8) {
        // ---- kept-reduce role: wait for all 72 gather blocks ----
        if (tid == 0) {
            while (atomicAdd(&g_gflag, 0u) < 72u) __nanosleep(32);
        }
        __syncthreads();
        __threadfence();
        const int b = blk;
        for (int d = tid; d < D_; d += TPB_) {
            float ks = 0.f;
            const float* kp = g_kpart + (size_t)b * GSLICE * D_ + d;
#pragma unroll
            for (int s = 0; s < GSLICE; s++) ks += kp[(size_t)s * D_];
            cold_out[b * D_ + d] = g_u[b * D_ + d] - CDROP_ * ks;
            g_kctx[b * D_ + d]   = ALPHA_ * ks;
        }
        __threadfence();
        __syncthreads();
        if (tid == 0) atomicAdd(&g_kflag, 1u);   // release kctx
    } else {
        // ---- gemv2 role (blocks 8..71): W loads overlap the gather ----
        float4* sctx = (float4*)smem_raw;
        const int e = (blk - 8) * 16 + warp;
        const float* wr = wread + (size_t)e * D_ + lane * 4;
        float4 w[8];
#pragma unroll
        for (int k = 0; k < 8; k++)
            w[k] = *(const float4*)(wr + k * 128);       // L2-hot

        if (tid == 0) {
            while (atomicAdd(&g_kflag, 0u) < 8u) __nanosleep(32);
        }
        __syncthreads();
        __threadfence();
        for (int i = tid; i < B_ * 256; i += TPB_)
            sctx[i] = ((const float4*)g_kctx)[i];
        __syncthreads();

        float acc[B_];
#pragma unroll
        for (int bb = 0; bb < B_; bb++) acc[bb] = 0.f;
#pragma unroll
        for (int k = 0; k < 8; k++) {
#pragma unroll
            for (int bb = 0; bb < B_; bb++) {
                float4 c = sctx[bb * 256 + k * 32 + lane];
                acc[bb] += w[k].x * c.x + w[k].y * c.y + w[k].z * c.z + w[k].w * c.w;
            }
        }
#pragma unroll
        for (int bb = 0; bb < B_; bb++) {
#pragma unroll
            for (int o = 16; o > 0; o >>= 1)
                acc[bb] += __shfl_down_sync(0xffffffffu, acc[bb], o);
            if (lane == 0) g_proj[bb * D_ + e] = g_proj1[bb * D_ + e] + acc[bb];
        }
    }
    // no final barrier — kernel boundary synchronizes before k_addproj
}

// ================= K2: addproj + barrier/flag reset for next replay =================
__global__ void __launch_bounds__(256)
k_addproj(const float* __restrict__ x, float* __restrict__ xout) {
    if (blockIdx.x == 0 && blockIdx.y == 0 && threadIdx.x < 11) {
        if (threadIdx.x < 8)       g_barrier[threadIdx.x] = 0u;
        else if (threadIdx.x == 8) g_uflag = 0u;
        else if (threadIdx.x == 9) g_kflag = 0u;
        else                       g_gflag = 0u;
    }
    const int b   = blockIdx.y;
    const int l0  = blockIdx.x * 32;
    const int tid = threadIdx.x;
    const float4 p = *(const float4*)(g_proj + b * D_ + tid * 4);
    const float* xs = x    + ((size_t)b * L_ + l0) * D_ + tid * 4;
    float*       os = xout + ((size_t)b * L_ + l0) * D_ + tid * 4;
#pragma unroll
    for (int rr = 0; rr < 32; rr += 8) {
        float4 v[8];
#pragma unroll
        for (int r = 0; r < 8; r++)
            v[r] = *(const float4*)(xs + (size_t)(rr + r) * D_);
#pragma unroll
        for (int r = 0; r < 8; r++) {
            v[r].x += p.x; v[r].y += p.y; v[r].z += p.z; v[r].w += p.w;
            *(float4*)(os + (size_t)(rr + r) * D_) = v[r];
        }
    }
}

// ---------------- launch ----------------
extern "C" void kernel_launch(void* const* d_in, const int* in_sizes, int n_in,
                              void* d_out, int out_size) {
    const float* x      = (const float*)d_in[0];   // [8,4096,1024]
    const float* active = (const float*)d_in[1];   // [8,256,1024]
    const float* cold   = (const float*)d_in[2];   // [8,1024]
    const float* w_sal  = (const float*)d_in[3];   // [1024]
    const float* w_read = (const float*)d_in[4];   // [1024,1024]

    float* xout       = (float*)d_out;
    float* new_active = xout + (size_t)in_sizes[0];
    float* cold_out   = new_active + (size_t)in_sizes[1];

    k_fused<<<GRID_, TPB_>>>(x, active, cold, w_sal, w_read,
                             new_active, cold_out);
    { dim3 grid(L_ / 32, B_); k_addproj<<<grid, 256>>>(x, xout); }
}

// round 17
// speedup vs baseline: 1.0268x; 1.0268x over previous
#include <cuda_runtime.h>
#include <cuda_bf16.h>
#include <stdint.h>

#define B_    8
#define L_    4096
#define D_    1024
#define A_    256
#define LC_   4352      // A_ + L_
#define KEEP_ 256
#define GRID_ 144       // <= SM count; one block per SM guaranteed
#define TPB_  512
#define BPB_  18        // blocks per batch in P0 (144/8)
#define NSLICE 18
#define SROWS 242       // ceil(4352/18)
#define GUNITS 128      // gather work units (8 batches x 16 units of 16 rows)
#define GSLICES 16      // kpart slices per batch

#define CDROP_ (0.1f / 4096.0f)                    // 0.1 / n_dropped
#define ALPHA_ (1.0f / 256.0f - 0.1f / 4096.0f)    // kept coefficient in ctx

// -------- scratch (device globals; zero-init at load; reset by k_addproj) --------
__device__ unsigned g_csal[B_];     // P0 arrivals per batch (18)
__device__ unsigned g_tflag[B_];    // topk done per batch
__device__ unsigned g_cgat[B_];     // gather units done per batch (16)
__device__ unsigned g_uflag;        // u vectors ready (8)
__device__ unsigned g_kflag;        // kctx ready (8)
__device__ unsigned g_wq;           // gather work-queue ticket
__device__ float g_sal[B_ * LC_];
__device__ float g_part[B_ * NSLICE * D_];
__device__ float g_kpart[B_ * GSLICES * D_];
__device__ int   g_topidx[B_ * KEEP_];
__device__ float g_u[B_ * D_];
__device__ float g_kctx[B_ * D_];
__device__ float g_proj1[B_ * D_];
__device__ float g_proj[B_ * D_];

__device__ __forceinline__ unsigned int order_key(float f) {
    unsigned int u = __float_as_uint(f);
    return u ^ ((u >> 31) ? 0xFFFFFFFFu : 0x80000000u);
}

// block-wide spin on a global counter reaching target (tid0 spins, broadcast)
__device__ __forceinline__ void block_wait(volatile unsigned* ctr, unsigned target) {
    if (threadIdx.x == 0) {
        while (atomicAdd((unsigned*)ctr, 0u) < target) __nanosleep(32);
    }
    __syncthreads();
    __threadfence();
}

// ---- gather work-stealing: drain the unit queue; returns when queue empty ----
__device__ void gather_drain(const float* __restrict__ x,
                             const float* __restrict__ active,
                             float* __restrict__ new_active,
                             float* s_col) {
    const int tid  = threadIdx.x;
    const int warp = tid >> 5;
    const int lane = tid & 31;
    __shared__ int s_unit;

    for (;;) {
        __syncthreads();
        if (tid == 0) {
            unsigned u = atomicAdd(&g_wq, 1u);
            s_unit = (u < GUNITS) ? (int)u : -1;
        }
        __syncthreads();
        const int u = s_unit;
        if (u < 0) return;
        const int b  = u & 7;
        const int sl = u >> 3;            // 0..15

        // wait for this batch's topk
        block_wait(&g_tflag[b], 1u);

        // zero partial
        for (int i = tid; i < D_; i += TPB_) s_col[i] = 0.f;
        __syncthreads();

        // 16 warps x 1 row each (16 rows per unit)
        const int r = sl * 16 + warp;
        const int idx = g_topidx[b * KEEP_ + r];
        const float* src = (idx < A_)
            ? active + ((size_t)b * A_ + idx) * D_
            : x      + ((size_t)b * L_ + (idx - A_)) * D_;
        float* dst = new_active + ((size_t)b * KEEP_ + r) * D_;
        float4 v[8];
#pragma unroll
        for (int k = 0; k < 8; k++)
            v[k] = *(const float4*)(src + k * 128 + lane * 4);
#pragma unroll
        for (int k = 0; k < 8; k++) {
            *(float4*)(dst + k * 128 + lane * 4) = v[k];
            int d0 = k * 128 + lane * 4;
            atomicAdd(&s_col[d0 + 0], v[k].x);
            atomicAdd(&s_col[d0 + 1], v[k].y);
            atomicAdd(&s_col[d0 + 2], v[k].z);
            atomicAdd(&s_col[d0 + 3], v[k].w);
        }
        __syncthreads();
        float* kp = g_kpart + ((size_t)b * GSLICES + sl) * D_;
        for (int i = tid; i < D_ / 4; i += TPB_)
            ((float4*)kp)[i] = ((const float4*)s_col)[i];
        __threadfence();
        __syncthreads();
        if (tid == 0) atomicAdd(&g_cgat[b], 1u);
    }
}

// ================= K1: persistent dataflow kernel =================
__global__ void __launch_bounds__(TPB_, 1)
k_fused(const float* __restrict__ x,
        const float* __restrict__ active,
        const float* __restrict__ cold,
        const float* __restrict__ wsal,
        const float* __restrict__ wread,
        float* __restrict__ new_active,
        float* __restrict__ cold_out) {
    __shared__ __align__(16) char smem_raw[33024];
    __shared__ unsigned s_prefix;
    __shared__ int s_krem;

    const int blk  = blockIdx.x;
    const int tid  = threadIdx.x;
    const int warp = tid >> 5;
    const int lane = tid & 31;

    //================ P0: salience + per-block partial column sums ================
    {
        float* s_col = (float*)smem_raw;
        const int b  = blk / BPB_;
        const int sl = blk % BPB_;
        for (int i = tid; i < D_; i += TPB_) s_col[i] = 0.f;

        float4 ws[8];
#pragma unroll
        for (int k = 0; k < 8; k++)
            ws[k] = *(const float4*)(wsal + k * 128 + lane * 4);
        float4 cs[8];
#pragma unroll
        for (int k = 0; k < 8; k++) cs[k] = make_float4(0.f, 0.f, 0.f, 0.f);
        __syncthreads();

        const int row0   = sl * SROWS;
        const int rowend = min(LC_, row0 + SROWS);
        for (int t = row0 + warp; t < rowend; t += 16) {
            const float* src = (t < A_)
                ? active + ((size_t)b * A_ + t) * D_
                : x      + ((size_t)b * L_ + (t - A_)) * D_;
            float dot = 0.f;
#pragma unroll
            for (int k = 0; k < 8; k++) {
                float4 v = *(const float4*)(src + k * 128 + lane * 4);
                dot += v.x * ws[k].x + v.y * ws[k].y + v.z * ws[k].z + v.w * ws[k].w;
                cs[k].x += v.x; cs[k].y += v.y; cs[k].z += v.z; cs[k].w += v.w;
            }
#pragma unroll
            for (int o = 16; o > 0; o >>= 1)
                dot += __shfl_down_sync(0xffffffffu, dot, o);
            if (lane == 0) g_sal[b * LC_ + t] = dot;
        }
#pragma unroll
        for (int k = 0; k < 8; k++) {
            int d0 = k * 128 + lane * 4;
            atomicAdd(&s_col[d0 + 0], cs[k].x);
            atomicAdd(&s_col[d0 + 1], cs[k].y);
            atomicAdd(&s_col[d0 + 2], cs[k].z);
            atomicAdd(&s_col[d0 + 3], cs[k].w);
        }
        __syncthreads();
        float* dst = g_part + ((size_t)b * NSLICE + sl) * D_;
        for (int i = tid; i < D_ / 4; i += TPB_)
            ((float4*)dst)[i] = ((const float4*)s_col)[i];
        __threadfence();
        __syncthreads();
        if (tid == 0) atomicAdd(&g_csal[b], 1u);   // per-batch release
    }

    //================ dataflow roles (no global barriers) ================
    if (blk < 8) {
        // ---- u-reduce for batch blk ----
        const int b = blk;
        block_wait(&g_csal[b], (unsigned)BPB_);
        for (int d = tid; d < D_; d += TPB_) {
            float tot = 0.f;
            const float* p = g_part + (size_t)b * NSLICE * D_ + d;
#pragma unroll
            for (int s = 0; s < NSLICE; s++) tot += p[(size_t)s * D_];
            g_u[b * D_ + d] = 0.9f * cold[b * D_ + d] + CDROP_ * tot;
        }
        __threadfence();
        __syncthreads();
        if (tid == 0) atomicAdd(&g_uflag, 1u);

        // help drain gather queue
        gather_drain(x, active, new_active, (float*)smem_raw);

        // kept-reduce for batch blk
        block_wait(&g_cgat[b], (unsigned)GSLICES);
        for (int d = tid; d < D_; d += TPB_) {
            float ks = 0.f;
            const float* kp = g_kpart + (size_t)b * GSLICES * D_ + d;
#pragma unroll
            for (int s = 0; s < GSLICES; s++) ks += kp[(size_t)s * D_];
            cold_out[b * D_ + d] = g_u[b * D_ + d] - CDROP_ * ks;
            g_kctx[b * D_ + d]   = ALPHA_ * ks;
        }
        __threadfence();
        __syncthreads();
        if (tid == 0) atomicAdd(&g_kflag, 1u);
    } else if (blk < 16) {
        // ---- topk for batch blk-8 ----
        const int b = blk - 8;
        block_wait(&g_csal[b], (unsigned)BPB_);

        unsigned* skeys = (unsigned*)smem_raw;              // 4352 u32
        unsigned* hist  = (unsigned*)(smem_raw + 17408);
        int* out_idx    = (int*)(smem_raw + 18432);
        unsigned* wsum  = (unsigned*)(smem_raw + 19456);

        for (int i = tid; i < LC_; i += TPB_)
            skeys[i] = order_key(g_sal[b * LC_ + i]);
        if (tid == 0) { s_prefix = 0u; s_krem = KEEP_; }
        __syncthreads();

        for (int pass = 0; pass < 4; pass++) {
            const int shift = 24 - 8 * pass;
            if (tid < 256) hist[tid] = 0u;
            __syncthreads();
            const unsigned pfx = s_prefix;
            const int krem = s_krem;
            for (int i = tid; i < LC_; i += TPB_) {
                unsigned k = skeys[i];
                if (pass == 0 || (k >> (shift + 8)) == pfx)
                    atomicAdd(&hist[(k >> shift) & 255u], 1u);
            }
            __syncthreads();
            if (warp == 0) {
                unsigned h[8], suf[8];
                unsigned acc = 0u;
#pragma unroll
                for (int j = 7; j >= 0; j--) { h[j] = hist[lane * 8 + j]; acc += h[j]; suf[j] = acc; }
                const unsigned tot = acc;
                unsigned inc = tot;
#pragma unroll
                for (int off = 1; off < 32; off <<= 1) {
                    unsigned v = __shfl_down_sync(0xffffffffu, inc, off);
                    if (lane + off < 32) inc += v;
                }
                const unsigned after = inc - tot;
#pragma unroll
                for (int j = 0; j < 8; j++) {
                    unsigned S  = after + suf[j];
                    unsigned Sn = after + (j < 7 ? suf[j + 1] : 0u);
                    if (S >= (unsigned)krem && Sn < (unsigned)krem) {
                        s_prefix = (pfx << 8) | (unsigned)(lane * 8 + j);
                        s_krem   = krem - (int)Sn;
                    }
                }
            }
            __syncthreads();
        }

        const unsigned thr = s_prefix;
        const unsigned rem = (unsigned)s_krem;

        const int base = tid * 9;
        unsigned keys_l[9];
        unsigned gt = 0u, eq = 0u;
#pragma unroll
        for (int j = 0; j < 9; j++) {
            const int i = base + j;
            unsigned k = (i < LC_) ? skeys[i] : 0u;
            keys_l[j] = k;
            if (i < LC_) { gt += (k > thr); eq += (k == thr); }
        }
        const unsigned pair = (gt << 16) | eq;
        unsigned inc = pair;
#pragma unroll
        for (int off = 1; off < 32; off <<= 1) {
            unsigned v = __shfl_up_sync(0xffffffffu, inc, off);
            if (lane >= off) inc += v;
        }
        const unsigned excl = inc - pair;
        if (lane == 31) wsum[warp] = inc;
        __syncthreads();
        if (warp == 0) {
            unsigned v = (lane < 16) ? wsum[lane] : 0u;
            unsigned winc = v;
#pragma unroll
            for (int off = 1; off < 16; off <<= 1) {
                unsigned t = __shfl_up_sync(0xffffffffu, winc, off);
                if (lane >= off) winc += t;
            }
            if (lane < 16) wsum[lane] = winc - v;
        }
        __syncthreads();
        const unsigned basepair = excl + wsum[warp];
        unsigned gpref = basepair >> 16;
        unsigned epref = basepair & 0xFFFFu;
#pragma unroll
        for (int j = 0; j < 9; j++) {
            const int i = base + j;
            if (i < LC_) {
                const unsigned k = keys_l[j];
                if (k > thr) {
                    out_idx[gpref + (epref < rem ? epref : rem)] = i;
                    gpref++;
                } else if (k == thr) {
                    if (epref < rem) out_idx[gpref + epref] = i;
                    epref++;
                }
            }
        }
        __syncthreads();
        if (tid < KEEP_) g_topidx[b * KEEP_ + tid] = out_idx[tid];
        __threadfence();
        __syncthreads();
        if (tid == 0) atomicExch(&g_tflag[b], 1u);

        // help drain gather queue, then done
        gather_drain(x, active, new_active, (float*)smem_raw);
    } else if (blk < 80) {
        // ---- gemv1: W front-batch (independent), wait u, FMA ----
        {
            float4* sctx = (float4*)smem_raw;
            const int e = (blk - 16) * 16 + warp;
            const float* wr = wread + (size_t)e * D_ + lane * 4;
            float4 w[8];
#pragma unroll
            for (int k = 0; k < 8; k++)
                w[k] = *(const float4*)(wr + k * 128);

            block_wait(&g_uflag, 8u);
            for (int i = tid; i < B_ * 256; i += TPB_)
                sctx[i] = ((const float4*)g_u)[i];
            __syncthreads();

            float acc[B_];
#pragma unroll
            for (int bb = 0; bb < B_; bb++) acc[bb] = 0.f;
#pragma unroll
            for (int k = 0; k < 8; k++) {
#pragma unroll
                for (int bb = 0; bb < B_; bb++) {
                    float4 c = sctx[bb * 256 + k * 32 + lane];
                    acc[bb] += w[k].x * c.x + w[k].y * c.y + w[k].z * c.z + w[k].w * c.w;
                }
            }
#pragma unroll
            for (int bb = 0; bb < B_; bb++) {
#pragma unroll
                for (int o = 16; o > 0; o >>= 1)
                    acc[bb] += __shfl_down_sync(0xffffffffu, acc[bb], o);
                if (lane == 0) g_proj1[bb * D_ + e] = acc[bb];
            }
        }
        __syncthreads();

        // help drain gather queue
        gather_drain(x, active, new_active, (float*)smem_raw);

        // ---- gemv2: W is L2-hot; wait kctx, FMA, write final proj ----
        {
            float4* sctx = (float4*)smem_raw;
            const int e = (blk - 16) * 16 + warp;
            const float* wr = wread + (size_t)e * D_ + lane * 4;
            float4 w[8];
#pragma unroll
            for (int k = 0; k < 8; k++)
                w[k] = *(const float4*)(wr + k * 128);

            block_wait(&g_kflag, 8u);
            for (int i = tid; i < B_ * 256; i += TPB_)
                sctx[i] = ((const float4*)g_kctx)[i];
            __syncthreads();

            float acc[B_];
#pragma unroll
            for (int bb = 0; bb < B_; bb++) acc[bb] = 0.f;
#pragma unroll
            for (int k = 0; k < 8; k++) {
#pragma unroll
                for (int bb = 0; bb < B_; bb++) {
                    float4 c = sctx[bb * 256 + k * 32 + lane];
                    acc[bb] += w[k].x * c.x + w[k].y * c.y + w[k].z * c.z + w[k].w * c.w;
                }
            }
#pragma unroll
            for (int bb = 0; bb < B_; bb++) {
#pragma unroll
                for (int o = 16; o > 0; o >>= 1)
                    acc[bb] += __shfl_down_sync(0xffffffffu, acc[bb], o);
                if (lane == 0) g_proj[bb * D_ + e] = g_proj1[bb * D_ + e] + acc[bb];
            }
        }
    } else {
        // ---- blocks 80..143: straight to gather queue ----
        gather_drain(x, active, new_active, (float*)smem_raw);
    }
    // kernel boundary synchronizes before k_addproj
}

// ================= K2: addproj + flag reset for next replay =================
__global__ void __launch_bounds__(256)
k_addproj(const float* __restrict__ x, float* __restrict__ xout) {
    if (blockIdx.x == 0 && blockIdx.y == 0) {
        const int t = threadIdx.x;
        if (t < 8)        g_csal[t]  = 0u;
        else if (t < 16)  g_tflag[t - 8] = 0u;
        else if (t < 24)  g_cgat[t - 16] = 0u;
        else if (t == 24) g_uflag = 0u;
        else if (t == 25) g_kflag = 0u;
        else if (t == 26) g_wq = 0u;
    }
    const int b   = blockIdx.y;
    const int l0  = blockIdx.x * 32;
    const int tid = threadIdx.x;
    const float4 p = *(const float4*)(g_proj + b * D_ + tid * 4);
    const float* xs = x    + ((size_t)b * L_ + l0) * D_ + tid * 4;
    float*       os = xout + ((size_t)b * L_ + l0) * D_ + tid * 4;
#pragma unroll
    for (int rr = 0; rr < 32; rr += 8) {
        float4 v[8];
#pragma unroll
        for (int r = 0; r < 8; r++)
            v[r] = *(const float4*)(xs + (size_t)(rr + r) * D_);
#pragma unroll
        for (int r = 0; r < 8; r++) {
            v[r].x += p.x; v[r].y += p.y; v[r].z += p.z; v[r].w += p.w;
            *(float4*)(os + (size_t)(rr + r) * D_) = v[r];
        }
    }
}

// ---------------- launch ----------------
extern "C" void kernel_launch(void* const* d_in, const int* in_sizes, int n_in,
                              void* d_out, int out_size) {
    const float* x      = (const float*)d_in[0];   // [8,4096,1024]
    const float* active = (const float*)d_in[1];   // [8,256,1024]
    const float* cold   = (const float*)d_in[2];   // [8,1024]
    const float* w_sal  = (const float*)d_in[3];   // [1024]
    const float* w_read = (const float*)d_in[4];   // [1024,1024]

    float* xout       = (float*)d_out;
    float* new_active = xout + (size_t)in_sizes[0];
    float* cold_out   = new_active + (size_t)in_sizes[1];

    k_fused<<<GRID_, TPB_>>>(x, active, cold, w_sal, w_read,
                             new_active, cold_out);
    { dim3 grid(L_ / 32, B_); k_addproj<<<grid, 256>>>(x, xout); }
}